// round 1
// baseline (speedup 1.0000x reference)
#include <cuda_runtime.h>
#include <cuda_bf16.h>

#define NN   100000
#define EE   1600000
#define FIN  64
#define FOUT 32

// -------- scratch (no allocations allowed) --------
__device__ float g_deg[NN];          // degree, then overwritten with d^{-1/2}
__device__ float g_agg[NN * FOUT];   // segment_sum(w_norm * h[col]) per row

// ---------------------------------------------------------------------------
// 1) zero deg + agg
// ---------------------------------------------------------------------------
__global__ void zero_kernel() {
    int i = blockIdx.x * blockDim.x + threadIdx.x;
    int tot = NN + NN * FOUT;
    if (i < tot) {
        if (i < NN) g_deg[i] = 0.0f;
        else        g_agg[i - NN] = 0.0f;
    }
}

// ---------------------------------------------------------------------------
// 2) deg[row] += edge_weight   (spread atomics, no return -> RED)
// ---------------------------------------------------------------------------
__global__ void deg_kernel(const int* __restrict__ ei, const float* __restrict__ ew) {
    int e = blockIdx.x * blockDim.x + threadIdx.x;
    if (e < EE) atomicAdd(&g_deg[ei[e]], ew[e]);
}

// ---------------------------------------------------------------------------
// 3) dis = deg > 0 ? rsqrt(deg) : 0   (in place)
// ---------------------------------------------------------------------------
__global__ void dis_kernel() {
    int n = blockIdx.x * blockDim.x + threadIdx.x;
    if (n < NN) {
        float v = g_deg[n];
        g_deg[n] = (v > 0.0f) ? rsqrtf(v) : 0.0f;
    }
}

// ---------------------------------------------------------------------------
// 4) SpMM scatter: agg[row] += (dis[row]*ew*dis[col]) * h[col]
//    one warp per edge, lane = feature (coalesced gather + coalesced RED)
// ---------------------------------------------------------------------------
__global__ void spmm_kernel(const int* __restrict__ ei,
                            const float* __restrict__ ew,
                            const float* __restrict__ h) {
    long long t = (long long)blockIdx.x * blockDim.x + threadIdx.x;
    int e = (int)(t >> 5);
    if (e >= EE) return;
    int f = (int)(t & 31);
    int r = ei[e];              // broadcast within warp
    int c = ei[EE + e];
    float w = g_deg[r] * ew[e] * g_deg[c];   // broadcast loads, L1/L2 hits
    float hv = h[c * FOUT + f];              // coalesced 128B row gather
    atomicAdd(&g_agg[r * FOUT + f], w * hv); // RED.E.ADD.F32, coalesced line
}

// ---------------------------------------------------------------------------
// 5) Fused dense: all 4 gate GEMMs + LSTM epilogue + relu + W_lin reduction
//    warp = 32 output features, 4 nodes per warp-iteration
// ---------------------------------------------------------------------------
__device__ __forceinline__ float sigf(float v) {
    return __fdividef(1.0f, 1.0f + __expf(-v));
}
__device__ __forceinline__ float tanh_(float v) {
    return fmaf(2.0f, sigf(2.0f * v), -1.0f);
}

#define SMEM_W4   (FIN * FOUT)         // 2048 float4 (W for 4 gates)
#define SMEM_T4   (FOUT * FOUT)        // 1024 float4 (theta[k] for 4 gates)
#define SMEM_BYTES ((SMEM_W4 + 2 * SMEM_T4 + FOUT) * 16 + FOUT * 4)

__global__ void __launch_bounds__(256) fused_kernel(
    const float* __restrict__ x,  const float* __restrict__ h,
    const float* __restrict__ c,
    const float* __restrict__ Wi, const float* __restrict__ bi,
    const float* __restrict__ thi, const float* __restrict__ cbi,
    const float* __restrict__ Wf, const float* __restrict__ bf,
    const float* __restrict__ thf, const float* __restrict__ cbf,
    const float* __restrict__ Wc, const float* __restrict__ bc,
    const float* __restrict__ thc, const float* __restrict__ cbc,
    const float* __restrict__ Wo, const float* __restrict__ bo,
    const float* __restrict__ tho, const float* __restrict__ cbo,
    const float* __restrict__ Wlin, const float* __restrict__ blin,
    float* __restrict__ out)
{
    extern __shared__ float4 sm[];
    float4* sW  = sm;                       // [FIN][FOUT] gate-interleaved
    float4* sT0 = sW  + SMEM_W4;            // [FOUT][FOUT]
    float4* sT1 = sT0 + SMEM_T4;            // [FOUT][FOUT]
    float4* sB  = sT1 + SMEM_T4;            // [FOUT] combined bias (b_g + cb_g)
    float*  sWl = (float*)(sB + FOUT);      // [FOUT]

    int tid = threadIdx.x;
    for (int i = tid; i < SMEM_W4; i += 256)
        sW[i] = make_float4(Wi[i], Wf[i], Wc[i], Wo[i]);
    for (int i = tid; i < SMEM_T4; i += 256) {
        sT0[i] = make_float4(thi[i],        thf[i],        thc[i],        tho[i]);
        sT1[i] = make_float4(thi[1024 + i], thf[1024 + i], thc[1024 + i], tho[1024 + i]);
    }
    if (tid < FOUT) {
        sB[tid] = make_float4(bi[tid] + cbi[tid], bf[tid] + cbf[tid],
                              bc[tid] + cbc[tid], bo[tid] + cbo[tid]);
        sWl[tid] = Wlin[tid];
    }
    __syncthreads();

    const float blin0 = __ldg(blin);
    int warp   = blockIdx.x * 8 + (tid >> 5);
    int lane   = tid & 31;
    int nwarps = gridDim.x * 8;

    const float4 bias = sB[lane];

    for (int base = warp * 4; base < NN; base += nwarps * 4) {
        float aI[4], aF[4], aC[4], aO[4];
        #pragma unroll
        for (int u = 0; u < 4; u++) {
            aI[u] = bias.x; aF[u] = bias.y; aC[u] = bias.z; aO[u] = bias.w;
        }
        const float* xr = x + base * FIN;
        const float* hr = h + base * FOUT;
        const float* ar = g_agg + base * FOUT;

        // x @ W_g  (K = 64)
        #pragma unroll 8
        for (int k = 0; k < FIN; k++) {
            float4 w = sW[k * FOUT + lane];
            #pragma unroll
            for (int u = 0; u < 4; u++) {
                float xv = __ldg(xr + u * FIN + k);     // warp broadcast
                aI[u] = fmaf(xv, w.x, aI[u]);
                aF[u] = fmaf(xv, w.y, aF[u]);
                aC[u] = fmaf(xv, w.z, aC[u]);
                aO[u] = fmaf(xv, w.w, aO[u]);
            }
        }
        // + h @ theta0_g  - agg @ theta1_g   (K = 32 each)
        #pragma unroll 8
        for (int j = 0; j < FOUT; j++) {
            float4 t0 = sT0[j * FOUT + lane];
            float4 t1 = sT1[j * FOUT + lane];
            #pragma unroll
            for (int u = 0; u < 4; u++) {
                float hv = __ldg(hr + u * FOUT + j);
                float av = __ldg(ar + u * FOUT + j);
                aI[u] = fmaf(hv, t0.x, aI[u]); aI[u] = fmaf(-av, t1.x, aI[u]);
                aF[u] = fmaf(hv, t0.y, aF[u]); aF[u] = fmaf(-av, t1.y, aF[u]);
                aC[u] = fmaf(hv, t0.z, aC[u]); aC[u] = fmaf(-av, t1.z, aC[u]);
                aO[u] = fmaf(hv, t0.w, aO[u]); aO[u] = fmaf(-av, t1.w, aO[u]);
            }
        }
        // LSTM epilogue + relu + Linear(32 -> 1) as warp reduction
        #pragma unroll
        for (int u = 0; u < 4; u++) {
            int n = base + u;
            if (n >= NN) break;
            float vI = sigf(aI[u]);
            float vF = sigf(aF[u]);
            float vT = tanh_(aC[u]);
            float vO = sigf(aO[u]);
            float cv = __ldg(c + n * FOUT + lane);
            float Cn = fmaf(vF, cv, vI * vT);
            float Hn = vO * tanh_(Cn);
            float val = fmaxf(Hn, 0.0f) * sWl[lane];
            #pragma unroll
            for (int o = 16; o > 0; o >>= 1)
                val += __shfl_xor_sync(0xffffffffu, val, o);
            if (lane == 0) out[n] = val + blin0;
        }
    }
}

// ---------------------------------------------------------------------------
extern "C" void kernel_launch(void* const* d_in, const int* in_sizes, int n_in,
                              void* d_out, int out_size)
{
    const float* x    = (const float*)d_in[0];
    const int*   ei   = (const int*)  d_in[1];
    const float* ew   = (const float*)d_in[2];
    const float* h    = (const float*)d_in[3];
    const float* c    = (const float*)d_in[4];
    const float* Wi   = (const float*)d_in[5];
    const float* bi   = (const float*)d_in[6];
    const float* thi  = (const float*)d_in[7];
    const float* cbi  = (const float*)d_in[8];
    const float* Wf   = (const float*)d_in[9];
    const float* bf   = (const float*)d_in[10];
    const float* thf  = (const float*)d_in[11];
    const float* cbf  = (const float*)d_in[12];
    const float* Wc   = (const float*)d_in[13];
    const float* bc   = (const float*)d_in[14];
    const float* thc  = (const float*)d_in[15];
    const float* cbc  = (const float*)d_in[16];
    const float* Wo   = (const float*)d_in[17];
    const float* bo   = (const float*)d_in[18];
    const float* tho  = (const float*)d_in[19];
    const float* cbo  = (const float*)d_in[20];
    const float* Wlin = (const float*)d_in[21];
    const float* blin = (const float*)d_in[22];
    float* out = (float*)d_out;

    cudaFuncSetAttribute(fused_kernel,
                         cudaFuncAttributeMaxDynamicSharedMemorySize, SMEM_BYTES);

    int tot = NN + NN * FOUT;
    zero_kernel<<<(tot + 511) / 512, 512>>>();
    deg_kernel<<<(EE + 255) / 256, 256>>>(ei, ew);
    dis_kernel<<<(NN + 255) / 256, 256>>>();
    // one warp per edge: EE * 32 threads
    long long spmm_threads = (long long)EE * 32;
    int spmm_blocks = (int)((spmm_threads + 255) / 256);
    spmm_kernel<<<spmm_blocks, 256>>>(ei, ew, h);
    fused_kernel<<<444, 256, SMEM_BYTES>>>(
        x, h, c,
        Wi, bi, thi, cbi,
        Wf, bf, thf, cbf,
        Wc, bc, thc, cbc,
        Wo, bo, tho, cbo,
        Wlin, blin, out);
}

// round 3
// speedup vs baseline: 1.0672x; 1.0672x over previous
#include <cuda_runtime.h>
#include <cuda_bf16.h>

#define NN   100000
#define EE   1600000
#define FIN  64
#define FOUT 32
#define NCHUNK 1024
#define NBLK  98            // ceil(NN / NCHUNK)

// -------- scratch (static __device__, no allocations) --------
__device__ __align__(16) float  g_deg[NN];            // degree -> d^{-1/2}
__device__ __align__(16) float  g_agg[NN * FOUT];     // gather result
__device__ int    g_cnt[NN];
__device__ int    g_incl[NBLK * NCHUNK];
__device__ int    g_bsum[NBLK + 2];
__device__ int    g_bscan[NBLK + 2];
__device__ int    g_rowptr[NN + 1];
__device__ int    g_cursor[NN];
__device__ __align__(16) float2 g_cw[EE];             // (col*FOUT as bits, w_norm)

// ---------------------------------------------------------------------------
__global__ void zero_kernel() {
    int i = blockIdx.x * blockDim.x + threadIdx.x;
    if (i < NN) { g_deg[i] = 0.0f; g_cnt[i] = 0; }
}

// deg[row] += ew ; cnt[row]++
__global__ void hist_kernel(const int* __restrict__ ei, const float* __restrict__ ew) {
    int e = blockIdx.x * blockDim.x + threadIdx.x;
    if (e < EE) {
        int r = ei[e];
        atomicAdd(&g_deg[r], ew[e]);
        atomicAdd(&g_cnt[r], 1);
    }
}

__global__ void dis_kernel() {
    int n = blockIdx.x * blockDim.x + threadIdx.x;
    if (n < NN) {
        float v = g_deg[n];
        g_deg[n] = (v > 0.0f) ? rsqrtf(v) : 0.0f;
    }
}

// per-1024-chunk inclusive scan of cnt
__global__ void __launch_bounds__(NCHUNK) scan_local_kernel() {
    __shared__ int s[NCHUNK];
    int tid = threadIdx.x;
    int i = blockIdx.x * NCHUNK + tid;
    s[tid] = (i < NN) ? g_cnt[i] : 0;
    __syncthreads();
    #pragma unroll
    for (int off = 1; off < NCHUNK; off <<= 1) {
        int t = (tid >= off) ? s[tid - off] : 0;
        __syncthreads();
        s[tid] += t;
        __syncthreads();
    }
    g_incl[i] = s[tid];
    if (tid == NCHUNK - 1) g_bsum[blockIdx.x] = s[tid];
}

// scan the 98 block sums (one block)
__global__ void scan_bsum_kernel() {
    __shared__ int s[128];
    int tid = threadIdx.x;
    s[tid] = (tid < NBLK) ? g_bsum[tid] : 0;
    __syncthreads();
    #pragma unroll
    for (int off = 1; off < 128; off <<= 1) {
        int t = (tid >= off) ? s[tid - off] : 0;
        __syncthreads();
        s[tid] += t;
        __syncthreads();
    }
    if (tid < NBLK) g_bscan[tid] = s[tid];
}

// rowptr (exclusive) + cursor
__global__ void scan_add_kernel() {
    int i = blockIdx.x * blockDim.x + threadIdx.x;
    if (i < NN) {
        int b = i >> 10;
        int off = b ? g_bscan[b - 1] : 0;
        int incl = g_incl[i] + off;
        g_rowptr[i + 1] = incl;
        g_cursor[i] = incl - g_cnt[i];
        if (i == 0) g_rowptr[0] = 0;
    }
}

// pack edges into CSR order: (col*FOUT, w_norm)
__global__ void scatter_kernel(const int* __restrict__ ei, const float* __restrict__ ew) {
    int e = blockIdx.x * blockDim.x + threadIdx.x;
    if (e < EE) {
        int r = ei[e];
        int c = ei[EE + e];
        float w = g_deg[r] * ew[e] * g_deg[c];
        int p = atomicAdd(&g_cursor[r], 1);
        g_cw[p] = make_float2(__int_as_float(c * FOUT), w);
    }
}

// gather SpMM: warp per row, lane = feature. No atomics.
__global__ void __launch_bounds__(256) gather_kernel(const float* __restrict__ h) {
    int warp = (blockIdx.x * 256 + threadIdx.x) >> 5;
    int lane = threadIdx.x & 31;
    if (warp >= NN) return;
    int beg = g_rowptr[warp];
    int end = g_rowptr[warp + 1];
    float acc = 0.0f;
    int e = beg;
    for (; e + 2 <= end; e += 2) {
        float2 a = g_cw[e];
        float2 b = g_cw[e + 1];
        float ha = h[__float_as_int(a.x) + lane];
        float hb = h[__float_as_int(b.x) + lane];
        acc = fmaf(a.y, ha, acc);
        acc = fmaf(b.y, hb, acc);
    }
    if (e < end) {
        float2 a = g_cw[e];
        acc = fmaf(a.y, h[__float_as_int(a.x) + lane], acc);
    }
    g_agg[warp * FOUT + lane] = acc;
}

// ---------------------------------------------------------------------------
// fused dense: packed f32x2 FMA along K
// ---------------------------------------------------------------------------
__device__ __forceinline__ unsigned long long pk(float lo, float hi) {
    unsigned long long r;
    asm("mov.b64 %0, {%1, %2};" : "=l"(r) : "f"(lo), "f"(hi));
    return r;
}
__device__ __forceinline__ void fma2(unsigned long long& d,
                                     unsigned long long a, unsigned long long b) {
    asm("fma.rn.f32x2 %0, %1, %2, %0;" : "+l"(d) : "l"(a), "l"(b));
}
__device__ __forceinline__ float hsum2(unsigned long long v) {
    float lo, hi;
    asm("mov.b64 {%0, %1}, %2;" : "=f"(lo), "=f"(hi) : "l"(v));
    return lo + hi;
}
__device__ __forceinline__ float sigf(float v) {
    return __fdividef(1.0f, 1.0f + __expf(-v));
}
__device__ __forceinline__ float tanh_(float v) {
    return fmaf(2.0f, sigf(2.0f * v), -1.0f);
}

#define UU 8   // nodes per warp-iteration
#define FUSED_SMEM (1024*16*2 + 512*16*4 + 32*16 + 32*4)

__global__ void __launch_bounds__(256) fused_kernel(
    const float* __restrict__ x,  const float* __restrict__ h,
    const float* __restrict__ c,
    const float* __restrict__ Wi, const float* __restrict__ bi,
    const float* __restrict__ thi, const float* __restrict__ cbi,
    const float* __restrict__ Wf, const float* __restrict__ bf,
    const float* __restrict__ thf, const float* __restrict__ cbf,
    const float* __restrict__ Wc, const float* __restrict__ bc,
    const float* __restrict__ thc, const float* __restrict__ cbc,
    const float* __restrict__ Wo, const float* __restrict__ bo,
    const float* __restrict__ tho, const float* __restrict__ cbo,
    const float* __restrict__ Wlin, const float* __restrict__ blin,
    float* __restrict__ out)
{
    extern __shared__ char smraw[];
    ulonglong2* sWIF  = (ulonglong2*)smraw;      // [kp(32)][lane(32)] (wI,wF) k-pairs
    ulonglong2* sWCO  = sWIF  + 1024;
    ulonglong2* sTIF0 = sWCO  + 1024;            // [jp(16)][lane] (tI0,tF0)
    ulonglong2* sTCO0 = sTIF0 + 512;
    ulonglong2* sTIF1 = sTCO0 + 512;             // pre-negated theta1
    ulonglong2* sTCO1 = sTIF1 + 512;
    float4*     sB    = (float4*)(sTCO1 + 512);  // combined bias per lane
    float*      sWl   = (float*)(sB + 32);

    int tid  = threadIdx.x;
    int lane = tid & 31;

    for (int i = tid; i < 1024; i += 256) {      // kp = i>>5, ln = i&31
        int kp = i >> 5, ln = i & 31;
        int i0 = kp * 64 + ln, i1 = kp * 64 + 32 + ln;
        sWIF[i] = make_ulonglong2(pk(Wi[i0], Wi[i1]), pk(Wf[i0], Wf[i1]));
        sWCO[i] = make_ulonglong2(pk(Wc[i0], Wc[i1]), pk(Wo[i0], Wo[i1]));
    }
    for (int i = tid; i < 512; i += 256) {       // jp = i>>5
        int jp = i >> 5, ln = i & 31;
        int i0 = jp * 64 + ln, i1 = jp * 64 + 32 + ln;
        sTIF0[i] = make_ulonglong2(pk(thi[i0], thi[i1]), pk(thf[i0], thf[i1]));
        sTCO0[i] = make_ulonglong2(pk(thc[i0], thc[i1]), pk(tho[i0], tho[i1]));
        sTIF1[i] = make_ulonglong2(pk(-thi[1024 + i0], -thi[1024 + i1]),
                                   pk(-thf[1024 + i0], -thf[1024 + i1]));
        sTCO1[i] = make_ulonglong2(pk(-thc[1024 + i0], -thc[1024 + i1]),
                                   pk(-tho[1024 + i0], -tho[1024 + i1]));
    }
    if (tid < FOUT) {
        sB[tid] = make_float4(bi[tid] + cbi[tid], bf[tid] + cbf[tid],
                              bc[tid] + cbc[tid], bo[tid] + cbo[tid]);
        sWl[tid] = Wlin[tid];
    }
    __syncthreads();

    const float  blin0 = __ldg(blin);
    const float4 bias  = sB[lane];
    int warp   = blockIdx.x * 8 + (tid >> 5);
    int nwarps = gridDim.x * 8;

    for (int base = warp * UU; base < NN; base += nwarps * UU) {
        unsigned long long accI[UU], accF[UU], accC[UU], accO[UU];
        #pragma unroll
        for (int u = 0; u < UU; u++) { accI[u]=0ull; accF[u]=0ull; accC[u]=0ull; accO[u]=0ull; }

        const ulonglong2* xp2 = (const ulonglong2*)(x + (size_t)base * FIN);   // 16 per row
        const ulonglong2* hp2 = (const ulonglong2*)(h + (size_t)base * FOUT);  // 8 per row
        const ulonglong2* ap2 = (const ulonglong2*)(g_agg + (size_t)base * FOUT);

        // x @ W : K = 64 (32 k-pairs, processed 2 per step)
        #pragma unroll 4
        for (int kk = 0; kk < 16; kk++) {
            ulonglong2 wIF0 = sWIF[(2*kk)   * 32 + lane];
            ulonglong2 wCO0 = sWCO[(2*kk)   * 32 + lane];
            ulonglong2 wIF1 = sWIF[(2*kk+1) * 32 + lane];
            ulonglong2 wCO1 = sWCO[(2*kk+1) * 32 + lane];
            #pragma unroll
            for (int u = 0; u < UU; u++) {
                ulonglong2 xv = xp2[u * 16 + kk];
                fma2(accI[u], xv.x, wIF0.x); fma2(accF[u], xv.x, wIF0.y);
                fma2(accC[u], xv.x, wCO0.x); fma2(accO[u], xv.x, wCO0.y);
                fma2(accI[u], xv.y, wIF1.x); fma2(accF[u], xv.y, wIF1.y);
                fma2(accC[u], xv.y, wCO1.x); fma2(accO[u], xv.y, wCO1.y);
            }
        }
        // + h @ theta0 - agg @ theta1 : K = 32 (16 j-pairs, 2 per step)
        #pragma unroll 2
        for (int jj = 0; jj < 8; jj++) {
            ulonglong2 tIF0a = sTIF0[(2*jj)   * 32 + lane];
            ulonglong2 tCO0a = sTCO0[(2*jj)   * 32 + lane];
            ulonglong2 tIF1a = sTIF1[(2*jj)   * 32 + lane];
            ulonglong2 tCO1a = sTCO1[(2*jj)   * 32 + lane];
            ulonglong2 tIF0b = sTIF0[(2*jj+1) * 32 + lane];
            ulonglong2 tCO0b = sTCO0[(2*jj+1) * 32 + lane];
            ulonglong2 tIF1b = sTIF1[(2*jj+1) * 32 + lane];
            ulonglong2 tCO1b = sTCO1[(2*jj+1) * 32 + lane];
            #pragma unroll
            for (int u = 0; u < UU; u++) {
                ulonglong2 hv = hp2[u * 8 + jj];
                ulonglong2 av = ap2[u * 8 + jj];
                fma2(accI[u], hv.x, tIF0a.x); fma2(accF[u], hv.x, tIF0a.y);
                fma2(accC[u], hv.x, tCO0a.x); fma2(accO[u], hv.x, tCO0a.y);
                fma2(accI[u], hv.y, tIF0b.x); fma2(accF[u], hv.y, tIF0b.y);
                fma2(accC[u], hv.y, tCO0b.x); fma2(accO[u], hv.y, tCO0b.y);
                fma2(accI[u], av.x, tIF1a.x); fma2(accF[u], av.x, tIF1a.y);
                fma2(accC[u], av.x, tCO1a.x); fma2(accO[u], av.x, tCO1a.y);
                fma2(accI[u], av.y, tIF1b.x); fma2(accF[u], av.y, tIF1b.y);
                fma2(accC[u], av.y, tCO1b.x); fma2(accO[u], av.y, tCO1b.y);
            }
        }
        // epilogue
        #pragma unroll
        for (int u = 0; u < UU; u++) {
            int n = base + u;
            if (n >= NN) break;
            float vI = sigf (hsum2(accI[u]) + bias.x);
            float vF = sigf (hsum2(accF[u]) + bias.y);
            float vT = tanh_(hsum2(accC[u]) + bias.z);
            float vO = sigf (hsum2(accO[u]) + bias.w);
            float cv = __ldg(c + (size_t)n * FOUT + lane);
            float Cn = fmaf(vF, cv, vI * vT);
            float Hn = vO * tanh_(Cn);
            float val = fmaxf(Hn, 0.0f) * sWl[lane];
            #pragma unroll
            for (int o = 16; o > 0; o >>= 1)
                val += __shfl_xor_sync(0xffffffffu, val, o);
            if (lane == 0) out[n] = val + blin0;
        }
    }
}

// ---------------------------------------------------------------------------
extern "C" void kernel_launch(void* const* d_in, const int* in_sizes, int n_in,
                              void* d_out, int out_size)
{
    const float* x    = (const float*)d_in[0];
    const int*   ei   = (const int*)  d_in[1];
    const float* ew   = (const float*)d_in[2];
    const float* h    = (const float*)d_in[3];
    const float* c    = (const float*)d_in[4];
    const float* Wi   = (const float*)d_in[5];
    const float* bi   = (const float*)d_in[6];
    const float* thi  = (const float*)d_in[7];
    const float* cbi  = (const float*)d_in[8];
    const float* Wf   = (const float*)d_in[9];
    const float* bf   = (const float*)d_in[10];
    const float* thf  = (const float*)d_in[11];
    const float* cbf  = (const float*)d_in[12];
    const float* Wc   = (const float*)d_in[13];
    const float* bc   = (const float*)d_in[14];
    const float* thc  = (const float*)d_in[15];
    const float* cbc  = (const float*)d_in[16];
    const float* Wo   = (const float*)d_in[17];
    const float* bo   = (const float*)d_in[18];
    const float* tho  = (const float*)d_in[19];
    const float* cbo  = (const float*)d_in[20];
    const float* Wlin = (const float*)d_in[21];
    const float* blin = (const float*)d_in[22];
    float* out = (float*)d_out;

    cudaFuncSetAttribute(fused_kernel,
                         cudaFuncAttributeMaxDynamicSharedMemorySize, FUSED_SMEM);

    zero_kernel<<<(NN + 511) / 512, 512>>>();
    hist_kernel<<<(EE + 255) / 256, 256>>>(ei, ew);
    dis_kernel<<<(NN + 255) / 256, 256>>>();
    scan_local_kernel<<<NBLK, NCHUNK>>>();
    scan_bsum_kernel<<<1, 128>>>();
    scan_add_kernel<<<(NN + 255) / 256, 256>>>();
    scatter_kernel<<<(EE + 255) / 256, 256>>>(ei, ew);
    gather_kernel<<<(NN * 32 + 255) / 256, 256>>>(h);
    fused_kernel<<<296, 256, FUSED_SMEM>>>(
        x, h, c,
        Wi, bi, thi, cbi,
        Wf, bf, thf, cbf,
        Wc, bc, thc, cbc,
        Wo, bo, tho, cbo,
        Wlin, blin, out);
}